// round 15
// baseline (speedup 1.0000x reference)
#include <cuda_runtime.h>
#include <cuda_fp16.h>
#include <cstdint>
#include <math_constants.h>

#define TOKENS  16384      // B*S
#define HDIM    4096
#define NEXP    64
#define MT      64         // tokens per CTA
#define KB      32         // k per stage (per group)
#define KSPLIT  2          // two K-groups of 8 warps
#define KG      (HDIM / KSPLIT)   // 2048 k per group
#define NST     (KG / KB)         // 64 stages per group
#define NK16    (KB / 16)         // 2
#define NTHREADS 512       // 2 groups x 8 warps (4 m x 2 n each)

// A: fp32, row stride 40 floats = 160B (20 float2 units, 20 mod 16 = 4 -> conflict-free LDS.64)
#define A_STRIDE 40
#define A_BYTES  (MT * A_STRIDE * 4)      // 10240
// B: packed half2 pairs {hi2,lo2}; row stride 20 uint2 (20 mod 16 = 4)
#define B_ROW_U2 20
#define B_BYTES  (NEXP * B_ROW_U2 * 8)    // 10240
#define STG_BYTES (A_BYTES + B_BYTES)     // 20480
#define NBUF 2
#define GRP_BYTES (NBUF * STG_BYTES)      // 40960
#define SMEM_TOTAL (KSPLIT * GRP_BYTES)   // 81920 per CTA -> 2 CTAs/SM

// loop-invariant: gate_w split into fp16 (hi,lo) half2-pairs, once per launch (1MB)
__device__ uint2 g_bsplit[NEXP * HDIM / 2];

__device__ __forceinline__ void cp_async16(void* sdst, const void* gsrc) {
    uint32_t s = (uint32_t)__cvta_generic_to_shared(sdst);
    asm volatile("cp.async.cg.shared.global [%0], [%1], 16;\n"
                 :: "r"(s), "l"(gsrc) : "memory");
}
__device__ __forceinline__ void cp_commit() {
    asm volatile("cp.async.commit_group;\n" ::: "memory");
}
template <int N>
__device__ __forceinline__ void cp_wait() {
    asm volatile("cp.async.wait_group %0;\n" :: "n"(N) : "memory");
}
__device__ __forceinline__ void bar_group(int g) {
    asm volatile("bar.sync %0, %1;" :: "r"(1 + g), "r"(256) : "memory");
}

// split a pair of fp32 into packed half2 hi and half2 lo (3xFP16 decomposition)
__device__ __forceinline__ void split_f16x2(float a, float b, uint32_t& hi2, uint32_t& lo2) {
    half2 h = __floats2half2_rn(a, b);
    float ra = a - __half2float(__low2half(h));
    float rb = b - __half2float(__high2half(h));
    half2 l = __floats2half2_rn(ra, rb);
    hi2 = *(uint32_t*)&h;
    lo2 = *(uint32_t*)&l;
}

__device__ __forceinline__ void mma_f16(float* d, const uint32_t* a, const uint32_t* b) {
    asm volatile(
        "mma.sync.aligned.m16n8k16.row.col.f32.f16.f16.f32 "
        "{%0,%1,%2,%3}, {%4,%5,%6,%7}, {%8,%9}, {%0,%1,%2,%3};"
        : "+f"(d[0]), "+f"(d[1]), "+f"(d[2]), "+f"(d[3])
        : "r"(a[0]), "r"(a[1]), "r"(a[2]), "r"(a[3]), "r"(b[0]), "r"(b[1]));
}

// ---- pre-kernel: split gate_w once into packed half2 (hi,lo) per k-pair ----
__global__ __launch_bounds__(256)
void split_b_kernel(const float* __restrict__ w)
{
    int i = blockIdx.x * 256 + threadIdx.x;
#pragma unroll
    for (int p = 0; p < 4; p++) {
        int pair = i + p * 32768;
        float2 v = *(const float2*)(w + (size_t)pair * 2);
        uint32_t hi2, lo2;
        split_f16x2(v.x, v.y, hi2, lo2);
        g_bsplit[pair] = make_uint2(hi2, lo2);
    }
}

__global__ __launch_bounds__(NTHREADS, 2)
void molora_router_mma(const float* __restrict__ x,
                       float* __restrict__ out)
{
    extern __shared__ char smem[];
    const int tid  = threadIdx.x;
    const int wid  = tid >> 5;
    const int lane = tid & 31;
    const int g    = wid >> 3;          // K-group 0/1
    const int wg   = wid & 7;           // warp within group
    const int wm   = wg & 3;            // m-tile 0..3 (16 tokens each)
    const int wn   = wg >> 2;           // expert half: wn*32 .. +31
    const int t256 = tid & 255;         // thread id within group
    const int m0   = blockIdx.x * MT;

    const int row = lane >> 2;
    const int qk  = lane & 3;

    char* gbase = smem + g * GRP_BYTES;

    float d[4][4];
#pragma unroll
    for (int ni = 0; ni < 4; ni++)
#pragma unroll
        for (int r = 0; r < 4; r++) d[ni][r] = 0.0f;

    // ---- async fill of group-local stage s into buffer buf ----
    auto fill = [&](int s, int buf) {
        char* Ab = gbase + buf * STG_BYTES;
        char* Bb = Ab + A_BYTES;
        const int k0 = g * KG + s * KB;
        // A: 64 tokens x 8 chunks of 16B -> 512 chunks, 2/thread (group threads)
#pragma unroll
        for (int p = 0; p < 2; p++) {
            int q = t256 + 256 * p;
            int token = q >> 3, kq = q & 7;
            cp_async16(Ab + token * (A_STRIDE * 4) + kq * 16,
                       x + (size_t)(m0 + token) * HDIM + k0 + kq * 4);
        }
        // B: 64 experts x 8 chunks (16 uint2) -> 512 chunks, 2/thread
#pragma unroll
        for (int p = 0; p < 2; p++) {
            int q = t256 + 256 * p;
            int exp = q >> 3, c = q & 7;
            cp_async16(Bb + exp * (B_ROW_U2 * 8) + c * 16,
                       g_bsplit + (size_t)exp * (HDIM / 2) + k0 / 2 + c * 2);
        }
        cp_commit();
    };

    // prologue: one stage in flight
    fill(0, 0);

    for (int s = 0; s < NST; s++) {
        const int buf = s & 1;
        cp_wait<0>();      // fill(s) complete (only one group ever outstanding)
        bar_group(g);      // data visible group-wide; stage s-1 readers (of the
                           // other buffer) have all passed -> safe to refill it
        if (s + 1 < NST) fill(s + 1, buf ^ 1);

        const float* Af = (const float*)(gbase + buf * STG_BYTES);
        const char*  Bb = (const char*)Af + A_BYTES;
        const int tb = wm * 16 + row;

#pragma unroll
        for (int k16 = 0; k16 < NK16; k16++) {
            uint32_t ahi[4], alo[4];
            {
                const float2* r0 = (const float2*)(Af + tb * A_STRIDE) + k16 * 8 + qk;
                const float2* r1 = (const float2*)(Af + (tb + 8) * A_STRIDE) + k16 * 8 + qk;
                float2 p0 = r0[0];
                float2 p1 = r1[0];
                float2 p2 = r0[4];
                float2 p3 = r1[4];
                split_f16x2(p0.x, p0.y, ahi[0], alo[0]);
                split_f16x2(p1.x, p1.y, ahi[1], alo[1]);
                split_f16x2(p2.x, p2.y, ahi[2], alo[2]);
                split_f16x2(p3.x, p3.y, ahi[3], alo[3]);
            }
            uint32_t bhi[4][2], blo[4][2];
#pragma unroll
            for (int ni = 0; ni < 4; ni++) {
                const int eb = (wn * 4 + ni) * 8 + row;
                const uint2* Brow = (const uint2*)(Bb + eb * (B_ROW_U2 * 8));
                uint2 g0 = Brow[k16 * 8 + qk];
                uint2 g1 = Brow[k16 * 8 + qk + 4];
                bhi[ni][0] = g0.x; blo[ni][0] = g0.y;
                bhi[ni][1] = g1.x; blo[ni][1] = g1.y;
            }
            // pass-major: 4 independent MMAs between accumulator reuses
#pragma unroll
            for (int ni = 0; ni < 4; ni++)
                mma_f16(d[ni], ahi, bhi[ni]);
#pragma unroll
            for (int ni = 0; ni < 4; ni++)
                mma_f16(d[ni], ahi, blo[ni]);
#pragma unroll
            for (int ni = 0; ni < 4; ni++)
                mma_f16(d[ni], alo, bhi[ni]);
        }
    }

    // ---- merge group 1's partial logits into group 0 ----
    __syncthreads();                       // all 512; buffers now dead
    float* Lx = (float*)smem;              // [64][68] partial logits, 17408B
    if (g == 1) {
#pragma unroll
        for (int ni = 0; ni < 4; ni++)
#pragma unroll
            for (int h = 0; h < 2; h++) {
                int tok = wm * 16 + row + h * 8;
                int col = wn * 32 + ni * 8 + qk * 2;
                *(float2*)&Lx[tok * 68 + col] =
                    make_float2(d[ni][h * 2], d[ni][h * 2 + 1]);
            }
    }
    __syncthreads();
    float4* red = (float4*)(smem + 17408);   // 64 tokens x 2 halves x 16B

    if (g == 0) {
#pragma unroll
        for (int ni = 0; ni < 4; ni++)
#pragma unroll
            for (int h = 0; h < 2; h++) {
                int tok = wm * 16 + row + h * 8;
                int col = wn * 32 + ni * 8 + qk * 2;
                float2 lv = *(const float2*)&Lx[tok * 68 + col];
                d[ni][h * 2]     += lv.x;
                d[ni][h * 2 + 1] += lv.y;
            }

        // per-warp top-2 over its 32 experts, quad reduce, publish candidates
#pragma unroll
        for (int h = 0; h < 2; h++) {
            float v1 = -CUDART_INF_F, v2 = -CUDART_INF_F;
            int i1 = 0, i2 = 0;
#pragma unroll
            for (int ni = 0; ni < 4; ni++)
#pragma unroll
                for (int r = 0; r < 2; r++) {
                    float v = d[ni][h * 2 + r];
                    int   e = (wn * 4 + ni) * 8 + qk * 2 + r;
                    if (v > v1)      { v2 = v1; i2 = i1; v1 = v; i1 = e; }
                    else if (v > v2) { v2 = v;  i2 = e; }
                }
#pragma unroll
            for (int mk = 1; mk <= 2; mk <<= 1) {
                float ov1 = __shfl_xor_sync(0xffffffffu, v1, mk);
                float ov2 = __shfl_xor_sync(0xffffffffu, v2, mk);
                int   oi1 = __shfl_xor_sync(0xffffffffu, i1, mk);
                int   oi2 = __shfl_xor_sync(0xffffffffu, i2, mk);
                bool o1_beats_m1 = (ov1 > v1) || (ov1 == v1 && oi1 < i1);
                if (o1_beats_m1) {
                    bool m1_beats_o2 = (v1 > ov2) || (v1 == ov2 && i1 < oi2);
                    v2 = m1_beats_o2 ? v1 : ov2;
                    i2 = m1_beats_o2 ? i1 : oi2;
                    v1 = ov1; i1 = oi1;
                } else {
                    bool o1_beats_m2 = (ov1 > v2) || (ov1 == v2 && oi1 < i2);
                    if (o1_beats_m2) { v2 = ov1; i2 = oi1; }
                }
            }
            if (qk == 0) {
                int tok = wm * 16 + row + h * 8;
                red[tok * 2 + wn] = make_float4(v1, v2, (float)i1, (float)i2);
            }
        }
    }
    __syncthreads();

    if (tid < MT) {
        float4 a = red[tid * 2 + 0];   // experts 0..31 (smaller indices)
        float4 b = red[tid * 2 + 1];   // experts 32..63
        float v1, v2; int i1, i2;
        if (a.x >= b.x) {
            v1 = a.x; i1 = (int)a.z;
            if (a.y >= b.x) { v2 = a.y; i2 = (int)a.w; }
            else            { v2 = b.x; i2 = (int)b.z; }
        } else {
            v1 = b.x; i1 = (int)b.z;
            if (a.x >= b.y) { v2 = a.x; i2 = (int)a.z; }
            else            { v2 = b.y; i2 = (int)b.w; }
        }
        float sfx = expf(v2 - v1);       // <= 1
        float inv = 1.0f / (1.0f + sfx);
        const int gt = m0 + tid;
        out[2 * gt + 0] = inv;
        out[2 * gt + 1] = sfx * inv;
        out[(size_t)TOKENS * 2 + 2 * gt + 0] = (float)i1;
        out[(size_t)TOKENS * 2 + 2 * gt + 1] = (float)i2;
    }
}

extern "C" void kernel_launch(void* const* d_in, const int* in_sizes, int n_in,
                              void* d_out, int out_size)
{
    const float* x = (const float*)d_in[0];      // [4,4096,4096] f32
    const float* w = (const float*)d_in[1];      // [64,4096]     f32
    float* out = (float*)d_out;

    (void)in_sizes; (void)n_in; (void)out_size;

    cudaFuncSetAttribute(molora_router_mma,
                         cudaFuncAttributeMaxDynamicSharedMemorySize, SMEM_TOTAL);

    // 1) split gate_w into fp16 hi/lo packed pairs (loop-invariant, 1MB)
    split_b_kernel<<<128, 256>>>(w);
    // 2) main GEMM + top-2 (split-K x2 per CTA, 2 CTAs/SM)
    molora_router_mma<<<TOKENS / MT, NTHREADS, SMEM_TOTAL>>>(x, out);
}